// round 1
// baseline (speedup 1.0000x reference)
#include <cuda_runtime.h>
#include <math_constants.h>

#define BATCH 16
#define NV    1024
#define NTOT  (BATCH * NV)

// Scratch (allocation-free: __device__ globals)
__device__ float4 g_cand[NTOT];  // {x, y, cos(psi), sin(psi)}
__device__ float  g_vel[NTOT];   // v

// ---------------------------------------------------------------------------
// Kernel 1: per-vehicle precompute. state layout: (B, NV*5), fields
// [x, y, v, psi, psidot] interleaved per vehicle.
// ---------------------------------------------------------------------------
__global__ void precompute_kernel(const float* __restrict__ state) {
    int t = blockIdx.x * blockDim.x + threadIdx.x;
    if (t >= NTOT) return;
    const float* s = state + (size_t)t * 5;
    float x = s[0], y = s[1], v = s[2], psi = s[3];
    float sn, cs;
    sincosf(psi, &sn, &cs);
    g_cand[t] = make_float4(x, y, cs, sn);
    g_vel[t]  = v;
}

// ---------------------------------------------------------------------------
// Kernel 2: warp-per-ego pairwise reduction.
//   blockDim = 256 (8 warps = 8 egos), grid = (NV/8, BATCH)
// ---------------------------------------------------------------------------
__global__ void __launch_bounds__(256) policy_kernel(
    const float* __restrict__ lengths,
    const float* __restrict__ v0p,
    const float* __restrict__ s0p,
    const float* __restrict__ dthp,
    const float* __restrict__ amaxp,
    const float* __restrict__ bp,
    float* __restrict__ out)
{
    const int warp = threadIdx.x >> 5;
    const int lane = threadIdx.x & 31;
    const int bat  = blockIdx.y;
    const int j    = (blockIdx.x << 3) + warp;   // ego index within batch
    const int base = bat * NV;

    // Ego data (broadcast loads, L1-resident)
    const float4 ego = g_cand[base + j];
    const float  vj  = g_vel[base + j];
    const float xj = ego.x, yj = ego.y, cj = ego.z, sj = ego.w;

    const float C20SQ = 0.8830222215594891f;   // cos^2(20 deg)
    const float C45   = 0.7071067811865476f;   // cos(45 deg)

    float best = CUDART_INF_F;   // min valid ndist (= projection)
    int   bidx = 0;              // argmin candidate index
    bool  stop = false;

    #pragma unroll 8
    for (int k = 0; k < NV / 32; ++k) {
        const int i = (k << 5) + lane;
        const float4 c4 = g_cand[base + i];
        const float  vi = g_vel[base + i];

        const float dx   = c4.x - xj;
        const float dy   = c4.y - yj;
        const float dr2  = dx * dx + dy * dy;
        const float proj = dx * cj + dy * sj;      // ndist = dr*cos(delpsi)
        const float p2   = proj * proj;
        const bool  pos  = proj > 0.0f;

        // valid leader: ndist > 0 && |delpsi| < 20deg
        const bool valid = pos && (p2 > dr2 * C20SQ);
        if (valid && proj < best) { best = proj; bidx = i; }

        // stop: dr < 20 && |delpsi| < 60deg && |dpsi| > 45deg && v_i > v_j
        const float cosd = c4.z * cj + c4.w * sj;  // cos(psi_i - psi_j)
        stop |= (dr2 < 400.0f) && pos && (4.0f * p2 > dr2)
                && (cosd < C45) && (vi > vj);
    }

    // Warp reductions: any(stop), min+argmin(best) with smaller-index ties
    stop = __any_sync(0xffffffffu, stop);
    #pragma unroll
    for (int off = 16; off > 0; off >>= 1) {
        const float ob = __shfl_down_sync(0xffffffffu, best, off);
        const int   oi = __shfl_down_sync(0xffffffffu, bidx, off);
        if (ob < best || (ob == best && oi < bidx)) { best = ob; bidx = oi; }
    }

    if (lane == 0) {
        const float v0   = v0p[0];
        const float s0   = s0p[0];
        const float dth  = dthp[0];
        const float amax = amaxp[0];
        const float bb   = bp[0];

        const float t  = vj / v0;
        const float t2 = t * t;
        const float action_free = amax * (1.0f - t2 * t2);
        const float sal = best - lengths[j];

        float action;
        if (stop) {
            // ratio = 1
            action = action_free - amax;
        } else if (isinf(sal)) {
            action = action_free;
        } else {
            const float4 l4 = g_cand[base + bidx];
            const float  vl = g_vel[base + bidx];
            const float dvx = vl * l4.z - vj * cj;
            const float dvy = vl * l4.w - vj * sj;
            const float ndv = dvx * cj + dvy * sj;       // dv*cos(vdelpsi)
            const float sstar = s0 + vj * dth + vj * ndv * (0.5f * rsqrtf(amax * bb));
            const float ratio = sstar / sal;
            action = action_free - amax * ratio * ratio;
        }
        out[base + j] = action;
    }
}

// ---------------------------------------------------------------------------
// Inputs (metadata order): state, lengths, v0, s0, dth, amax, b
// ---------------------------------------------------------------------------
extern "C" void kernel_launch(void* const* d_in, const int* in_sizes, int n_in,
                              void* d_out, int out_size) {
    const float* state   = (const float*)d_in[0];
    const float* lengths = (const float*)d_in[1];
    const float* v0      = (const float*)d_in[2];
    const float* s0      = (const float*)d_in[3];
    const float* dth     = (const float*)d_in[4];
    const float* amax    = (const float*)d_in[5];
    const float* b       = (const float*)d_in[6];
    float* out = (float*)d_out;

    precompute_kernel<<<NTOT / 256, 256>>>(state);

    dim3 grid(NV / 8, BATCH);
    policy_kernel<<<grid, 256>>>(lengths, v0, s0, dth, amax, b, out);
}